// round 11
// baseline (speedup 1.0000x reference)
#include <cuda_runtime.h>
#include <cuda_bf16.h>
#include <cstdint>

#define FULL_MASK 0xFFFFFFFFu

#define NSTAGE     6
#define CHUNK      4096                    // output elems per chunk
#define NCHUNK     32                      // 131072 / 4096
#define FLIP_BYTES (CHUNK * 4)             // 16384
#define EDC_BYTES  (CHUNK * 4 + 16)        // 16400: covers 16B-align shift + boundary elem
#define STAGE_TX   (FLIP_BYTES + EDC_BYTES)

// dynamic smem layout (all offsets 16B-aligned)
#define OFF_MBAR   0                       // 6 x 8B mbarriers
#define OFF_WPAR   64                      // 32 x u32 warp parities
#define OFF_WEXCL  192                     // 32 x u32 exclusive scans
#define OFF_CARRY  320                     // 2 x u32 ping-pong carry
#define OFF_FLIPS  512
#define OFF_EDC    (OFF_FLIPS + NSTAGE * FLIP_BYTES)    // 98816
#define SMEM_BYTES (OFF_EDC + NSTAGE * EDC_BYTES)       // 197216

static __device__ __forceinline__ float fast_sqrt(float x) {
    float y; asm("sqrt.approx.f32 %0, %1;" : "=f"(y) : "f"(x)); return y;
}
static __device__ __forceinline__ float apply_sign(float a, unsigned neg) {
    return __uint_as_float(__float_as_uint(a) ^ (neg << 31));
}
static __device__ __forceinline__ uint64_t make_evict_first_policy() {
    uint64_t p;
    asm("createpolicy.fractional.L2::evict_first.b64 %0, 1.0;" : "=l"(p));
    return p;
}
static __device__ __forceinline__ void mbar_init(uint32_t mbar, uint32_t cnt) {
    asm volatile("mbarrier.init.shared.b64 [%0], %1;" :: "r"(mbar), "r"(cnt) : "memory");
}
static __device__ __forceinline__ void mbar_expect_tx(uint32_t mbar, uint32_t tx) {
    asm volatile("mbarrier.arrive.expect_tx.shared.b64 _, [%0], %1;" :: "r"(mbar), "r"(tx) : "memory");
}
static __device__ __forceinline__ void mbar_wait(uint32_t mbar, uint32_t phase) {
    uint32_t done;
    asm volatile("{\n\t.reg .pred p;\n\t"
                 "mbarrier.try_wait.parity.acquire.cta.shared::cta.b64 p, [%1], %2;\n\t"
                 "selp.b32 %0, 1, 0, p;\n\t}"
                 : "=r"(done) : "r"(mbar), "r"(phase) : "memory");
    if (!done) {
        asm volatile("{\n\t.reg .pred P1;\n\t"
                     "W_%=:\n\t"
                     "mbarrier.try_wait.parity.acquire.cta.shared::cta.b64 P1, [%0], %1, 0x989680;\n\t"
                     "@P1 bra.uni D_%=;\n\t"
                     "bra.uni W_%=;\n\t"
                     "D_%=:\n\t}"
                     :: "r"(mbar), "r"(phase) : "memory");
    }
}
// Bulk copy with L2 evict-first hint.
static __device__ __forceinline__ void bulk_g2s(uint32_t dst, const void* src,
                                                uint32_t bytes, uint32_t mbar,
                                                uint64_t pol) {
    asm volatile("cp.async.bulk.shared::cluster.global.mbarrier::complete_tx::bytes"
                 ".L2::cache_hint [%0], [%1], %2, [%3], %4;"
                 :: "r"(dst), "l"(src), "r"(bytes), "r"(mbar), "l"(pol) : "memory");
}

// Whole-row worker specialized on the row's 16B misalignment O = (row mod 4).
template <int O>
static __device__ __forceinline__ void run_row(char* sm, uint32_t sbase,
                                               const char* edcAligned,
                                               const char* flipsRow,
                                               float4* out4row,
                                               int tid, int lane, int w,
                                               uint64_t pol)
{
    const unsigned lmask = (1u << lane) - 1u;
    uint32_t* sWarpPar  = (uint32_t*)(sm + OFF_WPAR);
    uint32_t* sWarpExcl = (uint32_t*)(sm + OFF_WEXCL);
    uint32_t* sCarry    = (uint32_t*)(sm + OFF_CARRY);

    int st = 0;
    unsigned ph = 0;

    #pragma unroll 1
    for (int c = 0; c < NCHUNK; c++) {
        const uint32_t mb = sbase + OFF_MBAR + st * 8;

        mbar_wait(mb, ph);                 // stage data (flips+edc) resident

        // ---- flips: parity structure for this thread's 4 elems ----
        const int4* fb = (const int4*)(sm + OFF_FLIPS + st * FLIP_BYTES);
        int4 fv = fb[tid];
        unsigned b0 = (unsigned)fv.x & 1u;
        unsigned b1 = (unsigned)fv.y & 1u;
        unsigned b2 = (unsigned)fv.z & 1u;
        unsigned b3 = (unsigned)fv.w & 1u;
        if (c == 0 && tid == 0) b0 = 0u;   // flips[:,0] never applied
        unsigned g  = b0 | (b1 << 1) | (b2 << 2) | (b3 << 3);
        unsigned gp = b0 ^ b1 ^ b2 ^ b3;

        unsigned bal      = __ballot_sync(FULL_MASK, gp);
        unsigned laneExcl = (unsigned)__popc(bal & lmask) & 1u;
        if (lane == 0) sWarpPar[w] = (unsigned)__popc(bal) & 1u;
        __syncthreads();
        if (w == 0) {
            unsigned p  = sWarpPar[lane];
            unsigned bw = __ballot_sync(FULL_MASK, p);
            sWarpExcl[lane] = (unsigned)__popc(bw & lmask) & 1u;
            if (lane == 0)
                sCarry[(c + 1) & 1] = sCarry[c & 1] ^ ((unsigned)__popc(bw) & 1u);
        }
        __syncthreads();
        const unsigned neg = (sCarry[c & 1] ^ sWarpExcl[w] ^ laneExcl) & 1u;

        unsigned incl = g;
        incl ^= incl << 1;
        incl ^= incl << 2;                 // inclusive prefix-XOR within the 4-group
        unsigned sgn = (incl ^ (neg ? 0xFu : 0u)) & 0xFu;

        // ---- edc: two aligned quads, static element select ----
        const float4* eb = (const float4*)(sm + OFF_EDC + st * EDC_BYTES);
        float4 qa = eb[tid];
        float4 qb = eb[tid + 1];
        float e0, e1, e2, e3, e4;
        if (O == 0)      { e0 = qa.x; e1 = qa.y; e2 = qa.z; e3 = qa.w; e4 = qb.x; }
        else if (O == 1) { e0 = qa.y; e1 = qa.z; e2 = qa.w; e3 = qb.x; e4 = qb.y; }
        else if (O == 2) { e0 = qa.z; e1 = qa.w; e2 = qb.x; e3 = qb.y; e4 = qb.z; }
        else             { e0 = qa.w; e1 = qb.x; e2 = qb.y; e3 = qb.z; e4 = qb.w; }

        float a0 = fast_sqrt(fmaxf(e0 - e1, 0.0f));
        float a1 = fast_sqrt(fmaxf(e1 - e2, 0.0f));
        float a2 = fast_sqrt(fmaxf(e2 - e3, 0.0f));
        float a3 = fast_sqrt(fmaxf(e3 - e4, 0.0f));

        float4 o;
        o.x = apply_sign(a0,  sgn       & 1u);
        o.y = apply_sign(a1, (sgn >> 1) & 1u);
        o.z = apply_sign(a2, (sgn >> 2) & 1u);
        o.w = apply_sign(a3, (sgn >> 3) & 1u);
        __stcs(out4row + (size_t)c * 1024 + tid, o);   // streaming (evict-first) store

        __syncthreads();                   // stage fully consumed -> reusable
        if (tid == 0) {
            int n = c + NSTAGE;
            if (n < NCHUNK) {
                mbar_expect_tx(mb, STAGE_TX);
                bulk_g2s(sbase + OFF_FLIPS + st * FLIP_BYTES,
                         flipsRow + (size_t)n * FLIP_BYTES, FLIP_BYTES, mb, pol);
                bulk_g2s(sbase + OFF_EDC + st * EDC_BYTES,
                         edcAligned + (size_t)n * (CHUNK * 4), EDC_BYTES, mb, pol);
            }
        }

        if (++st == NSTAGE) { st = 0; ph ^= 1u; }
    }
}

// One block per row. 1024 threads; 6-stage cp.async.bulk pipeline keeps
// ~197KB/SM of loads in flight; L2 evict-first on loads, streaming stores.
__global__ __launch_bounds__(1024, 1)
void SignStickyPhaseReconstructor_kernel(const float* __restrict__ edc,
                                         const int*   __restrict__ flips,
                                         float*       __restrict__ out)
{
    extern __shared__ char sm[];
    const uint32_t sbase = (uint32_t)__cvta_generic_to_shared(sm);

    const int tid  = threadIdx.x;
    const int lane = tid & 31;
    const int w    = tid >> 5;
    const int row  = blockIdx.x;
    const uint64_t pol = make_evict_first_policy();

    const char* edcRow = (const char*)(edc + (size_t)row * 131073);
    const uintptr_t ea = (uintptr_t)edcRow;
    const char* edcAligned = (const char*)(ea & ~(uintptr_t)15);
    const int o = (int)((ea & 15) >> 2);             // 0..3, uniform per block
    const char* flipsRow = (const char*)(flips + (size_t)row * 131072);
    float4* out4row = (float4*)(out + (size_t)row * 131072);

    if (tid == 0) {
        #pragma unroll
        for (int s = 0; s < NSTAGE; s++) mbar_init(sbase + OFF_MBAR + s * 8, 1);
        ((uint32_t*)(sm + OFF_CARRY))[0] = 0u;
        ((uint32_t*)(sm + OFF_CARRY))[1] = 0u;
    }
    __syncthreads();
    if (tid == 0) {
        asm volatile("fence.proxy.async.shared::cta;" ::: "memory");
        #pragma unroll
        for (int n = 0; n < NSTAGE; n++) {
            uint32_t mb = sbase + OFF_MBAR + n * 8;
            mbar_expect_tx(mb, STAGE_TX);
            bulk_g2s(sbase + OFF_FLIPS + n * FLIP_BYTES,
                     flipsRow + (size_t)n * FLIP_BYTES, FLIP_BYTES, mb, pol);
            bulk_g2s(sbase + OFF_EDC + n * EDC_BYTES,
                     edcAligned + (size_t)n * (CHUNK * 4), EDC_BYTES, mb, pol);
        }
    }

    switch (o) {
        case 0:  run_row<0>(sm, sbase, edcAligned, flipsRow, out4row, tid, lane, w, pol); break;
        case 1:  run_row<1>(sm, sbase, edcAligned, flipsRow, out4row, tid, lane, w, pol); break;
        case 2:  run_row<2>(sm, sbase, edcAligned, flipsRow, out4row, tid, lane, w, pol); break;
        default: run_row<3>(sm, sbase, edcAligned, flipsRow, out4row, tid, lane, w, pol); break;
    }
}

extern "C" void kernel_launch(void* const* d_in, const int* in_sizes, int n_in,
                              void* d_out, int out_size)
{
    const int B = 256, T = 131073;

    const float* edc;
    const int*   flips;
    if (in_sizes[0] == B * T) {
        edc   = (const float*)d_in[0];
        flips = (const int*)  d_in[1];
    } else {
        edc   = (const float*)d_in[1];
        flips = (const int*)  d_in[0];
    }
    float* out = (float*)d_out;

    cudaFuncSetAttribute(SignStickyPhaseReconstructor_kernel,
                         cudaFuncAttributeMaxDynamicSharedMemorySize, SMEM_BYTES);
    SignStickyPhaseReconstructor_kernel<<<B, 1024, SMEM_BYTES>>>(edc, flips, out);
}

// round 12
// speedup vs baseline: 1.0347x; 1.0347x over previous
#include <cuda_runtime.h>
#include <cuda_bf16.h>
#include <cstdint>

#define FULL_MASK 0xFFFFFFFFu

#define NSTAGE     4
#define CHUNK      4096                    // output elems per chunk
#define NCHUNK     32                      // 131072 / 4096
#define FLIP_BYTES (CHUNK * 4)             // 16384
#define EDC_BYTES  (CHUNK * 4 + 16)        // 16400: covers 16B-align shift + boundary elem
#define STAGE_TX   (FLIP_BYTES + EDC_BYTES)

// dynamic smem layout (all offsets 16B-aligned)
#define OFF_MBAR   0                       // 4 x 8B mbarriers
#define OFF_WPAR   64                      // 32 x u32 warp parities
#define OFF_WEXCL  192                     // 32 x u32 exclusive scans
#define OFF_CARRY  320                     // 2 x u32 ping-pong carry
#define OFF_FLIPS  512
#define OFF_EDC    (OFF_FLIPS + NSTAGE * FLIP_BYTES)    // 66048
#define SMEM_BYTES (OFF_EDC + NSTAGE * EDC_BYTES)       // 131648

static __device__ __forceinline__ float fast_sqrt(float x) {
    float y; asm("sqrt.approx.f32 %0, %1;" : "=f"(y) : "f"(x)); return y;
}
static __device__ __forceinline__ float apply_sign(float a, unsigned neg) {
    return __uint_as_float(__float_as_uint(a) ^ (neg << 31));
}
static __device__ __forceinline__ uint64_t make_evict_first_policy() {
    uint64_t p;
    asm("createpolicy.fractional.L2::evict_first.b64 %0, 1.0;" : "=l"(p));
    return p;
}
static __device__ __forceinline__ void mbar_init(uint32_t mbar, uint32_t cnt) {
    asm volatile("mbarrier.init.shared.b64 [%0], %1;" :: "r"(mbar), "r"(cnt) : "memory");
}
static __device__ __forceinline__ void mbar_expect_tx(uint32_t mbar, uint32_t tx) {
    asm volatile("mbarrier.arrive.expect_tx.shared.b64 _, [%0], %1;" :: "r"(mbar), "r"(tx) : "memory");
}
static __device__ __forceinline__ void mbar_wait(uint32_t mbar, uint32_t phase) {
    uint32_t done;
    asm volatile("{\n\t.reg .pred p;\n\t"
                 "mbarrier.try_wait.parity.acquire.cta.shared::cta.b64 p, [%1], %2;\n\t"
                 "selp.b32 %0, 1, 0, p;\n\t}"
                 : "=r"(done) : "r"(mbar), "r"(phase) : "memory");
    if (!done) {
        asm volatile("{\n\t.reg .pred P1;\n\t"
                     "W_%=:\n\t"
                     "mbarrier.try_wait.parity.acquire.cta.shared::cta.b64 P1, [%0], %1, 0x989680;\n\t"
                     "@P1 bra.uni D_%=;\n\t"
                     "bra.uni W_%=;\n\t"
                     "D_%=:\n\t}"
                     :: "r"(mbar), "r"(phase) : "memory");
    }
}
// Bulk copy with L2 evict-first hint: streamed read sectors become immediate
// eviction candidates instead of displacing pending write lines.
static __device__ __forceinline__ void bulk_g2s(uint32_t dst, const void* src,
                                                uint32_t bytes, uint32_t mbar,
                                                uint64_t pol) {
    asm volatile("cp.async.bulk.shared::cluster.global.mbarrier::complete_tx::bytes"
                 ".L2::cache_hint [%0], [%1], %2, [%3], %4;"
                 :: "r"(dst), "l"(src), "r"(bytes), "r"(mbar), "l"(pol) : "memory");
}

// Whole-row worker specialized on the row's 16B misalignment O = (row mod 4).
template <int O>
static __device__ __forceinline__ void run_row(char* sm, uint32_t sbase,
                                               const char* edcAligned,
                                               const char* flipsRow,
                                               float4* out4row,
                                               int tid, int lane, int w,
                                               uint64_t pol)
{
    const unsigned lmask = (1u << lane) - 1u;
    uint32_t* sWarpPar  = (uint32_t*)(sm + OFF_WPAR);
    uint32_t* sWarpExcl = (uint32_t*)(sm + OFF_WEXCL);
    uint32_t* sCarry    = (uint32_t*)(sm + OFF_CARRY);

    #pragma unroll 1
    for (int c = 0; c < NCHUNK; c++) {
        const int s        = c & (NSTAGE - 1);
        const uint32_t ph  = (unsigned)(c >> 2) & 1u;
        const uint32_t mb  = sbase + OFF_MBAR + s * 8;

        mbar_wait(mb, ph);                 // stage data (flips+edc) resident

        // ---- flips: parity structure for this thread's 4 elems ----
        const int4* fb = (const int4*)(sm + OFF_FLIPS + s * FLIP_BYTES);
        int4 fv = fb[tid];
        unsigned b0 = (unsigned)fv.x & 1u;
        unsigned b1 = (unsigned)fv.y & 1u;
        unsigned b2 = (unsigned)fv.z & 1u;
        unsigned b3 = (unsigned)fv.w & 1u;
        if (c == 0 && tid == 0) b0 = 0u;   // flips[:,0] never applied
        unsigned g  = b0 | (b1 << 1) | (b2 << 2) | (b3 << 3);
        unsigned gp = b0 ^ b1 ^ b2 ^ b3;

        unsigned bal      = __ballot_sync(FULL_MASK, gp);
        unsigned laneExcl = (unsigned)__popc(bal & lmask) & 1u;
        if (lane == 0) sWarpPar[w] = (unsigned)__popc(bal) & 1u;
        __syncthreads();
        if (w == 0) {
            unsigned p  = sWarpPar[lane];
            unsigned bw = __ballot_sync(FULL_MASK, p);
            sWarpExcl[lane] = (unsigned)__popc(bw & lmask) & 1u;
            if (lane == 0)
                sCarry[(c + 1) & 1] = sCarry[c & 1] ^ ((unsigned)__popc(bw) & 1u);
        }
        __syncthreads();
        const unsigned neg = (sCarry[c & 1] ^ sWarpExcl[w] ^ laneExcl) & 1u;

        unsigned incl = g;
        incl ^= incl << 1;
        incl ^= incl << 2;                 // inclusive prefix-XOR within the 4-group
        unsigned sgn = (incl ^ (neg ? 0xFu : 0u)) & 0xFu;

        // ---- edc: two aligned quads, static element select ----
        const float4* eb = (const float4*)(sm + OFF_EDC + s * EDC_BYTES);
        float4 qa = eb[tid];
        float4 qb = eb[tid + 1];
        float e0, e1, e2, e3, e4;
        if (O == 0)      { e0 = qa.x; e1 = qa.y; e2 = qa.z; e3 = qa.w; e4 = qb.x; }
        else if (O == 1) { e0 = qa.y; e1 = qa.z; e2 = qa.w; e3 = qb.x; e4 = qb.y; }
        else if (O == 2) { e0 = qa.z; e1 = qa.w; e2 = qb.x; e3 = qb.y; e4 = qb.z; }
        else             { e0 = qa.w; e1 = qb.x; e2 = qb.y; e3 = qb.z; e4 = qb.w; }

        float a0 = fast_sqrt(fmaxf(e0 - e1, 0.0f));
        float a1 = fast_sqrt(fmaxf(e1 - e2, 0.0f));
        float a2 = fast_sqrt(fmaxf(e2 - e3, 0.0f));
        float a3 = fast_sqrt(fmaxf(e3 - e4, 0.0f));

        float4 o;
        o.x = apply_sign(a0,  sgn       & 1u);
        o.y = apply_sign(a1, (sgn >> 1) & 1u);
        o.z = apply_sign(a2, (sgn >> 2) & 1u);
        o.w = apply_sign(a3, (sgn >> 3) & 1u);
        __stcs(out4row + (size_t)c * 1024 + tid, o);   // streaming (evict-first) store

        __syncthreads();                   // stage fully consumed -> reusable
        if (tid == 0) {
            int n = c + NSTAGE;
            if (n < NCHUNK) {
                mbar_expect_tx(mb, STAGE_TX);
                bulk_g2s(sbase + OFF_FLIPS + s * FLIP_BYTES,
                         flipsRow + (size_t)n * FLIP_BYTES, FLIP_BYTES, mb, pol);
                bulk_g2s(sbase + OFF_EDC + s * EDC_BYTES,
                         edcAligned + (size_t)n * (CHUNK * 4), EDC_BYTES, mb, pol);
            }
        }
    }
}

// One block per row. 1024 threads; 4-stage cp.async.bulk pipeline keeps
// ~131KB/SM of loads in flight; L2 evict-first on loads, streaming stores.
__global__ __launch_bounds__(1024, 1)
void SignStickyPhaseReconstructor_kernel(const float* __restrict__ edc,
                                         const int*   __restrict__ flips,
                                         float*       __restrict__ out)
{
    extern __shared__ char sm[];
    const uint32_t sbase = (uint32_t)__cvta_generic_to_shared(sm);

    const int tid  = threadIdx.x;
    const int lane = tid & 31;
    const int w    = tid >> 5;
    const int row  = blockIdx.x;
    const uint64_t pol = make_evict_first_policy();

    const char* edcRow = (const char*)(edc + (size_t)row * 131073);
    const uintptr_t ea = (uintptr_t)edcRow;
    const char* edcAligned = (const char*)(ea & ~(uintptr_t)15);
    const int o = (int)((ea & 15) >> 2);             // 0..3, uniform per block
    const char* flipsRow = (const char*)(flips + (size_t)row * 131072);
    float4* out4row = (float4*)(out + (size_t)row * 131072);

    if (tid == 0) {
        #pragma unroll
        for (int s = 0; s < NSTAGE; s++) mbar_init(sbase + OFF_MBAR + s * 8, 1);
        ((uint32_t*)(sm + OFF_CARRY))[0] = 0u;
        ((uint32_t*)(sm + OFF_CARRY))[1] = 0u;
    }
    __syncthreads();
    if (tid == 0) {
        asm volatile("fence.proxy.async.shared::cta;" ::: "memory");
        #pragma unroll
        for (int n = 0; n < NSTAGE; n++) {
            uint32_t mb = sbase + OFF_MBAR + n * 8;
            mbar_expect_tx(mb, STAGE_TX);
            bulk_g2s(sbase + OFF_FLIPS + n * FLIP_BYTES,
                     flipsRow + (size_t)n * FLIP_BYTES, FLIP_BYTES, mb, pol);
            bulk_g2s(sbase + OFF_EDC + n * EDC_BYTES,
                     edcAligned + (size_t)n * (CHUNK * 4), EDC_BYTES, mb, pol);
        }
    }

    switch (o) {
        case 0:  run_row<0>(sm, sbase, edcAligned, flipsRow, out4row, tid, lane, w, pol); break;
        case 1:  run_row<1>(sm, sbase, edcAligned, flipsRow, out4row, tid, lane, w, pol); break;
        case 2:  run_row<2>(sm, sbase, edcAligned, flipsRow, out4row, tid, lane, w, pol); break;
        default: run_row<3>(sm, sbase, edcAligned, flipsRow, out4row, tid, lane, w, pol); break;
    }
}

extern "C" void kernel_launch(void* const* d_in, const int* in_sizes, int n_in,
                              void* d_out, int out_size)
{
    const int B = 256, T = 131073;

    const float* edc;
    const int*   flips;
    if (in_sizes[0] == B * T) {
        edc   = (const float*)d_in[0];
        flips = (const int*)  d_in[1];
    } else {
        edc   = (const float*)d_in[1];
        flips = (const int*)  d_in[0];
    }
    float* out = (float*)d_out;

    cudaFuncSetAttribute(SignStickyPhaseReconstructor_kernel,
                         cudaFuncAttributeMaxDynamicSharedMemorySize, SMEM_BYTES);
    SignStickyPhaseReconstructor_kernel<<<B, 1024, SMEM_BYTES>>>(edc, flips, out);
}